// round 15
// baseline (speedup 1.0000x reference)
#include <cuda_runtime.h>
#include <cstdint>

#define Bn 4
#define Cn 256
#define Hn 224

// Band = 28 output rows; each CTA pipelines TWO consecutive bands.
// xs : 36 rows (x rows 28B-4 .. 28B+31), stride 228, slot s = cols 4s..4s+3 (no pads)
// d0s: 18 rows (global 14B-2 .. 14B+15), stride 120, data col 4+u, halos 3/116
// d1s:  9 rows (global 7B-1 .. 7B+7),   stride 64,  data col 4+v, halos 3/60
// t0s: 14 rows (global 14B .. 14B+13),  stride 116
#define XS_STRIDE 228
#define D0_STRIDE 120
#define D1_STRIDE 64
#define T0_STRIDE 116

#define XS_OFF 0
#define D0_OFF (36 * XS_STRIDE)                  // 8208
#define D1_OFF (D0_OFF + 18 * D0_STRIDE)         // 10368
#define T0_OFF (D1_OFF + 9 * D1_STRIDE)          // 10944
#define W_OFF  (T0_OFF + 14 * T0_STRIDE)         // 12568
#define SMEM_FLOATS (W_OFF + 32)                 // 12600 floats = 50400 B

__device__ __forceinline__ void cp_async16(float* dst, const float* src) {
    unsigned int d = (unsigned int)__cvta_generic_to_shared(dst);
    asm volatile("cp.async.cg.shared.global [%0], [%1], 16;\n" :: "r"(d), "l"(src));
}
__device__ __forceinline__ void cp_commit() {
    asm volatile("cp.async.commit_group;\n" ::: "memory");
}
__device__ __forceinline__ void cp_wait_all() {
    asm volatile("cp.async.wait_group 0;\n" ::: "memory");
}

// 6-wide window (cols 4q-1..4q+4) of x row y via LDG; edge cols via warp shuffle.
__device__ __forceinline__ void load_row_win(float* wrow, const float* __restrict__ xp,
                                             int y, int q, int lane) {
    float4 v = make_float4(0.f, 0.f, 0.f, 0.f);
    bool yv = (y >= 0) && (y < Hn);
    const float* row = xp + (size_t)y * Hn;
    if (yv) v = *(const float4*)(row + 4 * q);
    float lft = __shfl_up_sync(0xffffffffu, v.w, 1);
    float rgt = __shfl_down_sync(0xffffffffu, v.x, 1);
    if (lane == 0 && q > 0 && yv)   lft = row[4 * q - 1];
    if (lane == 31 && q < 55 && yv) rgt = row[4 * q + 4];
    if (q == 0)  lft = 0.f;
    if (q == 55) rgt = 0.f;
    wrow[0] = lft; wrow[1] = v.x; wrow[2] = v.y;
    wrow[3] = v.z; wrow[4] = v.w; wrow[5] = rgt;
}

__global__ void __launch_bounds__(256, 4)
kfused(const float* __restrict__ x,
       const float* __restrict__ bw,  const float* __restrict__ bb,
       const float* __restrict__ bs,  const float* __restrict__ wsv,
       const float* __restrict__ wll, const float* __restrict__ wlh1,
       const float* __restrict__ whl1,const float* __restrict__ whh1,
       const float* __restrict__ wlh0,const float* __restrict__ whl0,
       const float* __restrict__ whh0,
       float* __restrict__ out)
{
    extern __shared__ float smem[];
    float* xs  = smem + XS_OFF;
    float* d0s = smem + D0_OFF;
    float* d1s = smem + D1_OFF;
    float* t0s = smem + T0_OFF;
    float* wsh = smem + W_OFF;   // [0..8] ws1, [9..17] ws0, [18..26] base, 27 b, 28 bs, 29 ws

    int bx = blockIdx.x;
    int bc = bx >> 2;            // (batch,channel) plane
    int pr = bx & 3;             // band pair: bands 2pr, 2pr+1
    int c  = bc & (Cn - 1);
    int tid = threadIdx.x;
    float sR = (c & 64)  ? -1.f : 1.f;
    float sC = (c & 128) ? -1.f : 1.f;

    if (tid < 9) {
        int o = c * 9 + tid;
        wsh[tid]      = wll[o] + wlh1[o] + whl1[o] + whh1[o];
        wsh[9 + tid]  = wlh0[o] + whl0[o] + whh0[o];
        wsh[18 + tid] = bw[o];
    } else if (tid == 9)  wsh[27] = bb[c];
    else if (tid == 10)   wsh[28] = bs[c];
    else if (tid == 11)   wsh[29] = wsv[c];
    // zero col halos for d0s / d1s (stay zero across both bands)
    if (tid >= 64 && tid < 82) {
        int r = tid - 64;
        d0s[r * D0_STRIDE + 3]   = 0.f;
        d0s[r * D0_STRIDE + 116] = 0.f;
    } else if (tid >= 96 && tid < 105) {
        int r = tid - 96;
        d1s[r * D1_STRIDE + 3]  = 0.f;
        d1s[r * D1_STRIDE + 60] = 0.f;
    }

    const float* xp = x + (size_t)bc * Hn * Hn;

    // ---- prologue: prefetch band B0 = 2pr into xs ----
    {
        int B0 = 2 * pr;
        int X0 = 28 * B0 - 4;
        int lo = 0;
        if (B0 == 0) {           // rows 0..3 are y=-4..-1: zero them, skip fetch
            float4 z4 = make_float4(0.f, 0.f, 0.f, 0.f);
            for (int l = tid; l < 4 * 56; l += 256) {
                int r = l / 56, s = l % 56;
                ((float4*)(xs + r * XS_STRIDE))[s] = z4;
            }
            lo = 4 * 56;
        }
        for (int l = lo + tid; l < 36 * 56; l += 256) {
            int r = l / 56, s = l % 56;
            cp_async16(xs + r * XS_STRIDE + 4 * s, xp + (size_t)(X0 + r) * Hn + 4 * s);
        }
        cp_commit();
    }
    cp_wait_all();
    __syncthreads();

    float svb = (c & 128) ? -1.f : 1.f;
    float suo = (c & 64)  ? -1.f : 1.f;

    #pragma unroll 1
    for (int b = 0; b < 2; b++) {
        int B = 2 * pr + b;

        // ---- P1: decompose xs -> d0s, d1s; 504 items, pure LDS.128 ----
        for (int l = tid; l < 504; l += 256) {
            int wl = l / 56, j = l % 56;          // wl = d1 local row 0..8
            const float* base = xs + (4 * wl) * XS_STRIDE + 4 * j;
            float4 r0 = *(const float4*)(base);
            float4 r1 = *(const float4*)(base + XS_STRIDE);
            float4 r2 = *(const float4*)(base + 2 * XS_STRIDE);
            float4 r3 = *(const float4*)(base + 3 * XS_STRIDE);
            float d00 = 0.25f * (r0.x + sC * r0.y + sR * (r1.x + sC * r1.y));
            float d01 = 0.25f * (r0.z + sC * r0.w + sR * (r1.z + sC * r1.w));
            float d10 = 0.25f * (r2.x + sC * r2.y + sR * (r3.x + sC * r3.y));
            float d11 = 0.25f * (r2.z + sC * r2.w + sR * (r3.z + sC * r3.w));
            int m0 = 2 * wl;                       // d0 local rows m0, m0+1
            *(float2*)(d0s + m0 * D0_STRIDE + 4 + 2 * j)       = make_float2(d00, d01);
            *(float2*)(d0s + (m0 + 1) * D0_STRIDE + 4 + 2 * j) = make_float2(d10, d11);
            d1s[wl * D1_STRIDE + 4 + j] = 0.25f * (d00 + sC * d01 + sR * (d10 + sC * d11));
        }
        __syncthreads();

        // ---- prefetch band B1 = 2pr+1 while we compute band B0 ----
        if (b == 0) {
            int B1 = 2 * pr + 1;
            int X1 = 28 * B1 - 4;
            int hi = 36 * 56;
            if (B1 == 7) {       // rows 32..35 are y=224..227: zero, skip fetch
                float4 z4 = make_float4(0.f, 0.f, 0.f, 0.f);
                for (int l = tid; l < 4 * 56; l += 256) {
                    int r = 32 + l / 56, s = l % 56;
                    ((float4*)(xs + r * XS_STRIDE))[s] = z4;
                }
                hi = 32 * 56;
            }
            for (int l = tid; l < hi; l += 256) {
                int r = l / 56, s = l % 56;
                cp_async16(xs + r * XS_STRIDE + 4 * s, xp + (size_t)(X1 + r) * Hn + 4 * s);
            }
            cp_commit();
        }

        // ---- P2: s1 pair inline from d1s, then t0 = dw3x3(d0, ws0) + up(s1)*R_q ----
        if (tid < 196) {
            int mm = tid / 28, q = tid % 28;   // t0 local rows 2mm, 2mm+1
            float ww0 = wsh[0], ww1 = wsh[1], ww2 = wsh[2],
                  ww3 = wsh[3], ww4 = wsh[4], ww5 = wsh[5],
                  ww6 = wsh[6], ww7 = wsh[7], ww8 = wsh[8];
            float s1a, s1b;
            {
                const float* r0 = d1s + mm * D1_STRIDE + 3 + 2 * q;
                const float* r1 = r0 + D1_STRIDE;
                const float* r2 = r1 + D1_STRIDE;
                s1a = ww0*r0[0] + ww1*r0[1] + ww2*r0[2]
                    + ww3*r1[0] + ww4*r1[1] + ww5*r1[2]
                    + ww6*r2[0] + ww7*r2[1] + ww8*r2[2];
                s1b = ww0*r0[1] + ww1*r0[2] + ww2*r0[3]
                    + ww3*r1[1] + ww4*r1[2] + ww5*r1[3]
                    + ww6*r2[1] + ww7*r2[2] + ww8*r2[3];
            }
            float w0_[3], w1_[3], w2_[3];
            #pragma unroll
            for (int dy = 0; dy < 3; dy++) {
                w0_[dy] = wsh[9 + dy*3]; w1_[dy] = wsh[9 + dy*3 + 1]; w2_[dy] = wsh[9 + dy*3 + 2];
            }
            #pragma unroll
            for (int rr = 0; rr < 2; rr++) {
                float a0 = 0.f, a1 = 0.f, a2 = 0.f, a3 = 0.f;
                #pragma unroll
                for (int dy = 0; dy < 3; dy++) {
                    const float4* row4 = (const float4*)(d0s + (2 * mm + 1 + rr + dy) * D0_STRIDE);
                    float4 lq = row4[q], mq = row4[q + 1], rq = row4[q + 2];
                    a0 += w0_[dy] * lq.w + w1_[dy] * mq.x + w2_[dy] * mq.y;
                    a1 += w0_[dy] * mq.x + w1_[dy] * mq.y + w2_[dy] * mq.z;
                    a2 += w0_[dy] * mq.y + w1_[dy] * mq.z + w2_[dy] * mq.w;
                    a3 += w0_[dy] * mq.z + w1_[dy] * mq.w + w2_[dy] * rq.x;
                }
                float su = rr ? suo : 1.f;       // parity of global t0 row = rr
                float we = 0.5f * su, wo = we * svb;
                *(float4*)(t0s + (2 * mm + rr) * T0_STRIDE + 4 * q) =
                    make_float4(a0 + we * s1a, a1 + wo * s1a,
                                a2 + we * s1b, a3 + wo * s1b);
            }
        }
        __syncthreads();

        // ---- P4: out rows 28B..28B+27: 224 items (7 warps), 7 rows x 4 cols.
        //      x via LDG (L2-hot) + shuffle edges; xs untouched (prefetch target). ----
        if (tid < 224) {
            int rg = tid / 56, q = tid % 56;   // band-local rows 7rg..7rg+6
            int lane = tid & 31;
            float wb[9];
            #pragma unroll
            for (int i = 0; i < 9; i++) wb[i] = wsh[18 + i];
            float bias = wsh[27], bscale = wsh[28], wsc = wsh[29];
            float* op = out + (size_t)bc * Hn * Hn;

            float win[3][6];
            int n0g = 28 * B + 7 * rg;         // global first output row
            load_row_win(win[0], xp, n0g - 1, q, lane);
            load_row_win(win[1], xp, n0g,     q, lane);
            #pragma unroll
            for (int i = 0; i < 7; i++) {
                load_row_win(win[(i + 2) % 3], xp, n0g + 1 + i, q, lane);
                float a0 = 0.f, a1 = 0.f, a2 = 0.f, a3 = 0.f;
                #pragma unroll
                for (int dy = 0; dy < 3; dy++) {
                    const float* r = win[(i + dy) % 3];
                    float w0 = wb[dy*3], w1 = wb[dy*3+1], w2 = wb[dy*3+2];
                    a0 += w0 * r[0] + w1 * r[1] + w2 * r[2];
                    a1 += w0 * r[1] + w1 * r[2] + w2 * r[3];
                    a2 += w0 * r[2] + w1 * r[3] + w2 * r[4];
                    a3 += w0 * r[3] + w1 * r[4] + w2 * r[5];
                }
                int n = 7 * rg + i;            // band-local output row
                float2 tv = *(const float2*)(t0s + (n >> 1) * T0_STRIDE + 2 * q);
                float su = (n & 1) ? suo : 1.f;
                float we = wsc * 0.5f * su, wo = we * svb;
                float4 o4;
                o4.x = (a0 + bias) * bscale + we * tv.x;
                o4.y = (a1 + bias) * bscale + wo * tv.x;
                o4.z = (a2 + bias) * bscale + we * tv.y;
                o4.w = (a3 + bias) * bscale + wo * tv.y;
                *(float4*)(op + (size_t)(28 * B + n) * Hn + 4 * q) = o4;
            }
        }

        if (b == 0) {
            cp_wait_all();       // band B1 resident in xs
            __syncthreads();
        }
    }
}

extern "C" void kernel_launch(void* const* d_in, const int* in_sizes, int n_in,
                              void* d_out, int out_size) {
    const float* x          = (const float*)d_in[0];
    const float* base_w     = (const float*)d_in[1];
    const float* base_b     = (const float*)d_in[2];
    const float* base_scale = (const float*)d_in[3];
    const float* wav_scale  = (const float*)d_in[4];
    const float* w_ll       = (const float*)d_in[5];
    const float* w_lh0      = (const float*)d_in[6];
    const float* w_hl0      = (const float*)d_in[7];
    const float* w_hh0      = (const float*)d_in[8];
    const float* w_lh1      = (const float*)d_in[9];
    const float* w_hl1      = (const float*)d_in[10];
    const float* w_hh1      = (const float*)d_in[11];
    float* out = (float*)d_out;

    const int smemB = SMEM_FLOATS * sizeof(float);   // 50400 B
    cudaFuncSetAttribute(kfused, cudaFuncAttributeMaxDynamicSharedMemorySize, smemB);
    kfused<<<Bn * Cn * 4, 256, smemB>>>(x, base_w, base_b, base_scale, wav_scale,
                                        w_ll, w_lh1, w_hl1, w_hh1,
                                        w_lh0, w_hl0, w_hh0, out);
}

// round 16
// speedup vs baseline: 1.1016x; 1.1016x over previous
#include <cuda_runtime.h>
#include <cstdint>

#define Bn 4
#define Cn 256
#define Hn 224

// Band = 28 output rows, one band per CTA (R10 shape).
// xs : 30 rows (x rows 28B-1 .. 28B+28) for P4, stride 232,
//      float4 slot 1+s = cols 4s..4s+3, slots 0/57 zero pads.  cp.async-filled.
// d0s: 18 rows (global 14B-2 .. 14B+15), stride 120, data col 4+u, halos 3/116
// d1s:  9 rows (global 7B-1 .. 7B+7),   stride 64,  data col 4+v, halos 3/60
// t0s: 14 rows (global 14B .. 14B+13),  stride 116
#define XS_STRIDE 232
#define D0_STRIDE 120
#define D1_STRIDE 64
#define T0_STRIDE 116

#define XS_OFF 0
#define D0_OFF (30 * XS_STRIDE)                  // 6960
#define D1_OFF (D0_OFF + 18 * D0_STRIDE)         // 9120
#define T0_OFF (D1_OFF + 9 * D1_STRIDE)          // 9696
#define W_OFF  (T0_OFF + 14 * T0_STRIDE)         // 11320
#define SMEM_FLOATS (W_OFF + 32)                 // 11352 floats = 45408 B

__device__ __forceinline__ void cp_async16(float* dst, const float* src) {
    unsigned int d = (unsigned int)__cvta_generic_to_shared(dst);
    asm volatile("cp.async.cg.shared.global [%0], [%1], 16;\n" :: "r"(d), "l"(src));
}
__device__ __forceinline__ void cp_commit() {
    asm volatile("cp.async.commit_group;\n" ::: "memory");
}
__device__ __forceinline__ void cp_wait_all() {
    asm volatile("cp.async.wait_group 0;\n" ::: "memory");
}

__global__ void __launch_bounds__(256, 4)
kfused(const float* __restrict__ x,
       const float* __restrict__ bw,  const float* __restrict__ bb,
       const float* __restrict__ bs,  const float* __restrict__ wsv,
       const float* __restrict__ wll, const float* __restrict__ wlh1,
       const float* __restrict__ whl1,const float* __restrict__ whh1,
       const float* __restrict__ wlh0,const float* __restrict__ whl0,
       const float* __restrict__ whh0,
       float* __restrict__ out)
{
    extern __shared__ float smem[];
    float* xs  = smem + XS_OFF;
    float* d0s = smem + D0_OFF;
    float* d1s = smem + D1_OFF;
    float* t0s = smem + T0_OFF;
    float* wsh = smem + W_OFF;   // [0..8] ws1, [9..17] ws0, [18..26] base, 27 b, 28 bs, 29 ws

    int bx = blockIdx.x;
    int bc = bx >> 3;            // (batch,channel) plane
    int B  = bx & 7;             // band: out rows [28B, 28B+28)
    int c  = bc & (Cn - 1);
    int tid = threadIdx.x;
    float sR = (c & 64)  ? -1.f : 1.f;
    float sC = (c & 128) ? -1.f : 1.f;

    if (tid < 9) {
        int o = c * 9 + tid;
        wsh[tid]      = wll[o] + wlh1[o] + whl1[o] + whh1[o];
        wsh[9 + tid]  = wlh0[o] + whl0[o] + whh0[o];
        wsh[18 + tid] = bw[o];
    } else if (tid == 9)  wsh[27] = bb[c];
    else if (tid == 10)   wsh[28] = bs[c];
    else if (tid == 11)   wsh[29] = wsv[c];
    // xs side pads
    if (tid < 30) {
        float4 z4 = make_float4(0.f, 0.f, 0.f, 0.f);
        ((float4*)(xs + tid * XS_STRIDE))[0]  = z4;
        ((float4*)(xs + tid * XS_STRIDE))[57] = z4;
    }
    // d0s / d1s col halos
    if (tid >= 64 && tid < 82) {
        int r = tid - 64;
        d0s[r * D0_STRIDE + 3]   = 0.f;
        d0s[r * D0_STRIDE + 116] = 0.f;
    } else if (tid >= 96 && tid < 105) {
        int r = tid - 96;
        d1s[r * D1_STRIDE + 3]  = 0.f;
        d1s[r * D1_STRIDE + 60] = 0.f;
    }

    const float* xp = x + (size_t)bc * Hn * Hn;

    // ---- P0: fire-and-forget async prefetch of P4's x rows (28B-1 .. 28B+28) ----
    {
        int Xp = 28 * B - 1;
        float4 z4 = make_float4(0.f, 0.f, 0.f, 0.f);
        for (int l = tid; l < 30 * 56; l += 256) {
            int r = l / 56, s = l % 56;
            int y = Xp + r;
            float* dst = xs + r * XS_STRIDE + 4 + 4 * s;
            if (y >= 0 && y < Hn) cp_async16(dst, xp + (size_t)y * Hn + 4 * s);
            else                  *(float4*)dst = z4;
        }
        cp_commit();
    }

    int X0 = 28 * B - 4;   // x row of d0 local row 0 (pair start)
    bool safe = (B >= 1) && (B <= 6);

    // ---- P1: decompose x -> d0s (18 rows), d1s (9 rows); 504 items, LDG ----
    for (int l = tid; l < 504; l += 256) {
        int wl = l / 56, j = l % 56;          // wl = d1 local row 0..8
        int y0 = X0 + 4 * wl;
        const float* p = xp + (size_t)y0 * Hn + 4 * j;
        float4 r0, r1, r2, r3;
        if (safe) {
            r0 = *(const float4*)(p);
            r1 = *(const float4*)(p + Hn);
            r2 = *(const float4*)(p + 2 * Hn);
            r3 = *(const float4*)(p + 3 * Hn);
        } else {
            float4 z4 = make_float4(0.f, 0.f, 0.f, 0.f);
            r0 = (y0     >= 0 && y0     < Hn) ? *(const float4*)(p)          : z4;
            r1 = (y0 + 1 >= 0 && y0 + 1 < Hn) ? *(const float4*)(p + Hn)     : z4;
            r2 = (y0 + 2 >= 0 && y0 + 2 < Hn) ? *(const float4*)(p + 2 * Hn) : z4;
            r3 = (y0 + 3 >= 0 && y0 + 3 < Hn) ? *(const float4*)(p + 3 * Hn) : z4;
        }
        float d00 = 0.25f * (r0.x + sC * r0.y + sR * (r1.x + sC * r1.y));
        float d01 = 0.25f * (r0.z + sC * r0.w + sR * (r1.z + sC * r1.w));
        float d10 = 0.25f * (r2.x + sC * r2.y + sR * (r3.x + sC * r3.y));
        float d11 = 0.25f * (r2.z + sC * r2.w + sR * (r3.z + sC * r3.w));
        int m0 = 2 * wl;                       // d0 local rows m0, m0+1 (0..17)
        *(float2*)(d0s + m0 * D0_STRIDE + 4 + 2 * j)       = make_float2(d00, d01);
        *(float2*)(d0s + (m0 + 1) * D0_STRIDE + 4 + 2 * j) = make_float2(d10, d11);
        d1s[wl * D1_STRIDE + 4 + j] = 0.25f * (d00 + sC * d01 + sR * (d10 + sC * d11));
    }
    __syncthreads();

    // ---- P2: s1 pair inline from d1s, then t0 = dw3x3(d0, ws0) + up(s1)*R_q;
    //      196 items, 2 t0 rows each ----
    float svb = (c & 128) ? -1.f : 1.f;
    float suo = (c & 64)  ? -1.f : 1.f;
    if (tid < 196) {
        int mm = tid / 28, q = tid % 28;   // t0 local rows 2mm, 2mm+1
        float ww0 = wsh[0], ww1 = wsh[1], ww2 = wsh[2],
              ww3 = wsh[3], ww4 = wsh[4], ww5 = wsh[5],
              ww6 = wsh[6], ww7 = wsh[7], ww8 = wsh[8];
        float s1a, s1b;
        {
            const float* r0 = d1s + mm * D1_STRIDE + 3 + 2 * q;
            const float* r1 = r0 + D1_STRIDE;
            const float* r2 = r1 + D1_STRIDE;
            s1a = ww0*r0[0] + ww1*r0[1] + ww2*r0[2]
                + ww3*r1[0] + ww4*r1[1] + ww5*r1[2]
                + ww6*r2[0] + ww7*r2[1] + ww8*r2[2];
            s1b = ww0*r0[1] + ww1*r0[2] + ww2*r0[3]
                + ww3*r1[1] + ww4*r1[2] + ww5*r1[3]
                + ww6*r2[1] + ww7*r2[2] + ww8*r2[3];
        }
        float w0_[3], w1_[3], w2_[3];
        #pragma unroll
        for (int dy = 0; dy < 3; dy++) {
            w0_[dy] = wsh[9 + dy*3]; w1_[dy] = wsh[9 + dy*3 + 1]; w2_[dy] = wsh[9 + dy*3 + 2];
        }
        #pragma unroll
        for (int rr = 0; rr < 2; rr++) {
            float a0 = 0.f, a1 = 0.f, a2 = 0.f, a3 = 0.f;
            #pragma unroll
            for (int dy = 0; dy < 3; dy++) {
                const float4* row4 = (const float4*)(d0s + (2 * mm + 1 + rr + dy) * D0_STRIDE);
                float4 lq = row4[q], mq = row4[q + 1], rq = row4[q + 2];
                a0 += w0_[dy] * lq.w + w1_[dy] * mq.x + w2_[dy] * mq.y;
                a1 += w0_[dy] * mq.x + w1_[dy] * mq.y + w2_[dy] * mq.z;
                a2 += w0_[dy] * mq.y + w1_[dy] * mq.z + w2_[dy] * mq.w;
                a3 += w0_[dy] * mq.z + w1_[dy] * mq.w + w2_[dy] * rq.x;
            }
            float su = rr ? suo : 1.f;       // parity of global t0 row = rr
            float we = 0.5f * su, wo = we * svb;
            *(float4*)(t0s + (2 * mm + rr) * T0_STRIDE + 4 * q) =
                make_float4(a0 + we * s1a, a1 + wo * s1a,
                            a2 + we * s1b, a3 + wo * s1b);
        }
    }
    cp_wait_all();               // xs resident (had all of P1+P2 to land)
    __syncthreads();

    // ---- P4: out rows 28B..28B+27: 224 items (7 warps), 7 rows x 4 cols.
    //      Pure conflict-free LDS.128 from prefetched xs; rolling window. ----
    if (tid < 224) {
        int rg = tid / 56, q = tid % 56;   // band-local rows 7rg..7rg+6
        float wb[9];
        #pragma unroll
        for (int i = 0; i < 9; i++) wb[i] = wsh[18 + i];
        float bias = wsh[27], bscale = wsh[28], wsc = wsh[29];
        float* op = out + (size_t)bc * Hn * Hn;

        // out local row n uses xs rows n..n+2 (xs row r = x row 28B-1+r)
        float win[3][6];
        #pragma unroll
        for (int pk = 0; pk < 2; pk++) {
            const float4* r4 = (const float4*)(xs + (7 * rg + pk) * XS_STRIDE);
            float4 lq = r4[q], mq = r4[q + 1], rq = r4[q + 2];
            float* w = win[pk];
            w[0] = lq.w; w[1] = mq.x; w[2] = mq.y;
            w[3] = mq.z; w[4] = mq.w; w[5] = rq.x;
        }
        #pragma unroll
        for (int i = 0; i < 7; i++) {
            {
                const float4* r4 = (const float4*)(xs + (7 * rg + 2 + i) * XS_STRIDE);
                float4 lq = r4[q], mq = r4[q + 1], rq = r4[q + 2];
                float* w = win[(i + 2) % 3];
                w[0] = lq.w; w[1] = mq.x; w[2] = mq.y;
                w[3] = mq.z; w[4] = mq.w; w[5] = rq.x;
            }
            float a0 = 0.f, a1 = 0.f, a2 = 0.f, a3 = 0.f;
            #pragma unroll
            for (int dy = 0; dy < 3; dy++) {
                const float* r = win[(i + dy) % 3];
                float w0 = wb[dy*3], w1 = wb[dy*3+1], w2 = wb[dy*3+2];
                a0 += w0 * r[0] + w1 * r[1] + w2 * r[2];
                a1 += w0 * r[1] + w1 * r[2] + w2 * r[3];
                a2 += w0 * r[2] + w1 * r[3] + w2 * r[4];
                a3 += w0 * r[3] + w1 * r[4] + w2 * r[5];
            }
            int n = 7 * rg + i;            // band-local output row
            float2 tv = *(const float2*)(t0s + (n >> 1) * T0_STRIDE + 2 * q);
            float su = (n & 1) ? suo : 1.f;
            float we = wsc * 0.5f * su, wo = we * svb;
            float4 o4;
            o4.x = (a0 + bias) * bscale + we * tv.x;
            o4.y = (a1 + bias) * bscale + wo * tv.x;
            o4.z = (a2 + bias) * bscale + we * tv.y;
            o4.w = (a3 + bias) * bscale + wo * tv.y;
            *(float4*)(op + (size_t)(28 * B + n) * Hn + 4 * q) = o4;
        }
    }
}

extern "C" void kernel_launch(void* const* d_in, const int* in_sizes, int n_in,
                              void* d_out, int out_size) {
    const float* x          = (const float*)d_in[0];
    const float* base_w     = (const float*)d_in[1];
    const float* base_b     = (const float*)d_in[2];
    const float* base_scale = (const float*)d_in[3];
    const float* wav_scale  = (const float*)d_in[4];
    const float* w_ll       = (const float*)d_in[5];
    const float* w_lh0      = (const float*)d_in[6];
    const float* w_hl0      = (const float*)d_in[7];
    const float* w_hh0      = (const float*)d_in[8];
    const float* w_lh1      = (const float*)d_in[9];
    const float* w_hl1      = (const float*)d_in[10];
    const float* w_hh1      = (const float*)d_in[11];
    float* out = (float*)d_out;

    const int smemB = SMEM_FLOATS * sizeof(float);   // 45408 B
    cudaFuncSetAttribute(kfused, cudaFuncAttributeMaxDynamicSharedMemorySize, smemB);
    kfused<<<Bn * Cn * 8, 256, smemB>>>(x, base_w, base_b, base_scale, wav_scale,
                                        w_ll, w_lh1, w_hl1, w_hh1,
                                        w_lh0, w_hl0, w_hh0, out);
}

// round 17
// speedup vs baseline: 1.2163x; 1.1041x over previous
#include <cuda_runtime.h>

#define Bn 4
#define Cn 256
#define Hn 224

// Band = 28 output rows, 128-thread CTAs, 8 CTAs/SM.
// d0s: 18 rows (global 14B-2 .. 14B+15), stride 120, data col 4+u, halos 3/116
// d1s:  9 rows (global 7B-1 .. 7B+7),   stride 64,  data col 4+v, halos 3/60
// s1s:  7 rows (global 7B .. 7B+6),     stride 56
// t0s: 14 rows (global 14B .. 14B+13),  stride 116
#define D0_STRIDE 120
#define D1_STRIDE 64
#define S1_STRIDE 56
#define T0_STRIDE 116

// 6-wide window (cols 4q-1..4q+4) of x row y; edge cols via warp shuffle.
__device__ __forceinline__ void load_row_win(float* wrow, const float* __restrict__ xp,
                                             int y, int q, int lane) {
    float4 v = make_float4(0.f, 0.f, 0.f, 0.f);
    bool yv = (y >= 0) && (y < Hn);
    const float* row = xp + (size_t)y * Hn;
    if (yv) v = *(const float4*)(row + 4 * q);
    float lft = __shfl_up_sync(0xffffffffu, v.w, 1);
    float rgt = __shfl_down_sync(0xffffffffu, v.x, 1);
    if (lane == 0 && q > 0 && yv)   lft = row[4 * q - 1];
    if (lane == 31 && q < 55 && yv) rgt = row[4 * q + 4];
    if (q == 0)  lft = 0.f;
    if (q == 55) rgt = 0.f;
    wrow[0] = lft; wrow[1] = v.x; wrow[2] = v.y;
    wrow[3] = v.z; wrow[4] = v.w; wrow[5] = rgt;
}

__global__ void __launch_bounds__(128, 8)
kfused(const float* __restrict__ x,
       const float* __restrict__ bw,  const float* __restrict__ bb,
       const float* __restrict__ bs,  const float* __restrict__ wsv,
       const float* __restrict__ wll, const float* __restrict__ wlh1,
       const float* __restrict__ whl1,const float* __restrict__ whh1,
       const float* __restrict__ wlh0,const float* __restrict__ whl0,
       const float* __restrict__ whh0,
       float* __restrict__ out)
{
    __shared__ float d0s[18 * D0_STRIDE];
    __shared__ float d1s[9 * D1_STRIDE];
    __shared__ float s1s[7 * S1_STRIDE];
    __shared__ float t0s[14 * T0_STRIDE];
    __shared__ float wsh[32];  // [0..8] ws1, [9..17] ws0, [18..26] base, 27 b, 28 bs, 29 ws

    int bx = blockIdx.x;
    int bc = bx >> 3;            // (batch,channel) plane
    int B  = bx & 7;             // band: out rows [28B, 28B+28)
    int c  = bc & (Cn - 1);
    int tid = threadIdx.x;
    float sR = (c & 64)  ? -1.f : 1.f;
    float sC = (c & 128) ? -1.f : 1.f;

    if (tid < 9) {
        int o = c * 9 + tid;
        wsh[tid]      = wll[o] + wlh1[o] + whl1[o] + whh1[o];
        wsh[9 + tid]  = wlh0[o] + whl0[o] + whh0[o];
        wsh[18 + tid] = bw[o];
    } else if (tid == 9)  wsh[27] = bb[c];
    else if (tid == 10)   wsh[28] = bs[c];
    else if (tid == 11)   wsh[29] = wsv[c];
    // zero col halos
    if (tid >= 32 && tid < 50) {
        int r = tid - 32;
        d0s[r * D0_STRIDE + 3]   = 0.f;
        d0s[r * D0_STRIDE + 116] = 0.f;
    } else if (tid >= 64 && tid < 73) {
        int r = tid - 64;
        d1s[r * D1_STRIDE + 3]  = 0.f;
        d1s[r * D1_STRIDE + 60] = 0.f;
    }

    const float* xp = x + (size_t)bc * Hn * Hn;
    int X0 = 28 * B - 4;   // x row of d0 local row 0 (pair start)
    bool safe = (B >= 1) && (B <= 6);   // x rows X0..X0+35 all in [0,224)

    // ---- P1: decompose x -> d0s (18 rows), d1s (9 rows); 504 items ----
    for (int l = tid; l < 504; l += 128) {
        int wl = l / 56, j = l % 56;          // wl = d1 local row 0..8
        int y0 = X0 + 4 * wl;
        const float* p = xp + (size_t)y0 * Hn + 4 * j;
        float4 r0, r1, r2, r3;
        if (safe) {
            r0 = *(const float4*)(p);
            r1 = *(const float4*)(p + Hn);
            r2 = *(const float4*)(p + 2 * Hn);
            r3 = *(const float4*)(p + 3 * Hn);
        } else {
            float4 z4 = make_float4(0.f, 0.f, 0.f, 0.f);
            r0 = (y0     >= 0 && y0     < Hn) ? *(const float4*)(p)          : z4;
            r1 = (y0 + 1 >= 0 && y0 + 1 < Hn) ? *(const float4*)(p + Hn)     : z4;
            r2 = (y0 + 2 >= 0 && y0 + 2 < Hn) ? *(const float4*)(p + 2 * Hn) : z4;
            r3 = (y0 + 3 >= 0 && y0 + 3 < Hn) ? *(const float4*)(p + 3 * Hn) : z4;
        }
        float d00 = 0.25f * (r0.x + sC * r0.y + sR * (r1.x + sC * r1.y));
        float d01 = 0.25f * (r0.z + sC * r0.w + sR * (r1.z + sC * r1.w));
        float d10 = 0.25f * (r2.x + sC * r2.y + sR * (r3.x + sC * r3.y));
        float d11 = 0.25f * (r2.z + sC * r2.w + sR * (r3.z + sC * r3.w));
        int m0 = 2 * wl;                       // d0 local rows m0, m0+1 (0..17)
        *(float2*)(d0s + m0 * D0_STRIDE + 4 + 2 * j)       = make_float2(d00, d01);
        *(float2*)(d0s + (m0 + 1) * D0_STRIDE + 4 + 2 * j) = make_float2(d10, d11);
        d1s[wl * D1_STRIDE + 4 + j] = 0.25f * (d00 + sC * d01 + sR * (d10 + sC * d11));
    }
    __syncthreads();

    // ---- P2: s1 = dw3x3(d1, ws1): 98 items (7 rows x 14 qcols) ----
    if (tid < 98) {
        int m = tid / 14, q = tid % 14;
        float a0 = 0.f, a1 = 0.f, a2 = 0.f, a3 = 0.f;
        #pragma unroll
        for (int dy = 0; dy < 3; dy++) {
            const float4* row4 = (const float4*)(d1s + (m + dy) * D1_STRIDE);
            float4 lq = row4[q], mq = row4[q + 1], rq = row4[q + 2];
            float w0 = wsh[dy*3], w1 = wsh[dy*3+1], w2 = wsh[dy*3+2];
            a0 += w0 * lq.w + w1 * mq.x + w2 * mq.y;
            a1 += w0 * mq.x + w1 * mq.y + w2 * mq.z;
            a2 += w0 * mq.y + w1 * mq.z + w2 * mq.w;
            a3 += w0 * mq.z + w1 * mq.w + w2 * rq.x;
        }
        *(float4*)(s1s + m * S1_STRIDE + 4 * q) = make_float4(a0, a1, a2, a3);
    }
    __syncthreads();

    // ---- P3: t0 = dw3x3(d0, ws0) + up(s1)*R_q: 196 items, 2 t0 rows each ----
    float svb = (c & 128) ? -1.f : 1.f;
    float suo = (c & 64)  ? -1.f : 1.f;
    #pragma unroll
    for (int it = 0; it < 2; it++) {
        int item = tid + it * 128;
        if (item < 196) {
            int mm = item / 28, q = item % 28;   // t0 local rows 2mm, 2mm+1
            float rw[4][6];
            #pragma unroll
            for (int k = 0; k < 4; k++) {
                // d0 local rows 2mm+1 .. 2mm+4
                const float4* row4 = (const float4*)(d0s + (2 * mm + 1 + k) * D0_STRIDE);
                float4 lq = row4[q], mq = row4[q + 1], rq = row4[q + 2];
                rw[k][0] = lq.w; rw[k][1] = mq.x; rw[k][2] = mq.y;
                rw[k][3] = mq.z; rw[k][4] = mq.w; rw[k][5] = rq.x;
            }
            float2 sv = *(const float2*)(s1s + mm * S1_STRIDE + 2 * q);
            #pragma unroll
            for (int rr = 0; rr < 2; rr++) {
                float a0 = 0.f, a1 = 0.f, a2 = 0.f, a3 = 0.f;
                #pragma unroll
                for (int dy = 0; dy < 3; dy++) {
                    const float* r = rw[rr + dy];
                    float w0 = wsh[9 + dy*3], w1 = wsh[9 + dy*3 + 1], w2 = wsh[9 + dy*3 + 2];
                    a0 += w0 * r[0] + w1 * r[1] + w2 * r[2];
                    a1 += w0 * r[1] + w1 * r[2] + w2 * r[3];
                    a2 += w0 * r[2] + w1 * r[3] + w2 * r[4];
                    a3 += w0 * r[3] + w1 * r[4] + w2 * r[5];
                }
                float su = rr ? suo : 1.f;       // parity of global t0 row = rr
                float we = 0.5f * su, wo = we * svb;
                *(float4*)(t0s + (2 * mm + rr) * T0_STRIDE + 4 * q) =
                    make_float4(a0 + we * sv.x, a1 + wo * sv.x,
                                a2 + we * sv.y, a3 + wo * sv.y);
            }
        }
    }
    __syncthreads();

    // ---- P4: out rows 28B..28B+27: 224 items, 7 rows x 4 cols each;
    //      2 stride passes (pass 2: warps 0-2 full, warp 3 idle) ----
    #pragma unroll
    for (int it = 0; it < 2; it++) {
        int item = tid + it * 128;
        if (item < 224) {
            int rg = item / 56, q = item % 56;   // band-local rows 7rg..7rg+6
            int lane = tid & 31;
            float wb[9];
            #pragma unroll
            for (int i = 0; i < 9; i++) wb[i] = wsh[18 + i];
            float bias = wsh[27], bscale = wsh[28], wsc = wsh[29];
            float* op = out + (size_t)bc * Hn * Hn;

            float win[3][6];
            int n0g = 28 * B + 7 * rg;         // global first output row
            load_row_win(win[0], xp, n0g - 1, q, lane);
            load_row_win(win[1], xp, n0g,     q, lane);
            #pragma unroll
            for (int i = 0; i < 7; i++) {
                load_row_win(win[(i + 2) % 3], xp, n0g + 1 + i, q, lane);
                float a0 = 0.f, a1 = 0.f, a2 = 0.f, a3 = 0.f;
                #pragma unroll
                for (int dy = 0; dy < 3; dy++) {
                    const float* r = win[(i + dy) % 3];
                    float w0 = wb[dy*3], w1 = wb[dy*3+1], w2 = wb[dy*3+2];
                    a0 += w0 * r[0] + w1 * r[1] + w2 * r[2];
                    a1 += w0 * r[1] + w1 * r[2] + w2 * r[3];
                    a2 += w0 * r[2] + w1 * r[3] + w2 * r[4];
                    a3 += w0 * r[3] + w1 * r[4] + w2 * r[5];
                }
                int n = 7 * rg + i;            // band-local output row
                float2 tv = *(const float2*)(t0s + (n >> 1) * T0_STRIDE + 2 * q);
                float su = (n & 1) ? suo : 1.f;
                float we = wsc * 0.5f * su, wo = we * svb;
                float4 o4;
                o4.x = (a0 + bias) * bscale + we * tv.x;
                o4.y = (a1 + bias) * bscale + wo * tv.x;
                o4.z = (a2 + bias) * bscale + we * tv.y;
                o4.w = (a3 + bias) * bscale + wo * tv.y;
                *(float4*)(op + (size_t)(28 * B + n) * Hn + 4 * q) = o4;
            }
        }
    }
}

extern "C" void kernel_launch(void* const* d_in, const int* in_sizes, int n_in,
                              void* d_out, int out_size) {
    const float* x          = (const float*)d_in[0];
    const float* base_w     = (const float*)d_in[1];
    const float* base_b     = (const float*)d_in[2];
    const float* base_scale = (const float*)d_in[3];
    const float* wav_scale  = (const float*)d_in[4];
    const float* w_ll       = (const float*)d_in[5];
    const float* w_lh0      = (const float*)d_in[6];
    const float* w_hl0      = (const float*)d_in[7];
    const float* w_hh0      = (const float*)d_in[8];
    const float* w_lh1      = (const float*)d_in[9];
    const float* w_hl1      = (const float*)d_in[10];
    const float* w_hh1      = (const float*)d_in[11];
    float* out = (float*)d_out;

    kfused<<<Bn * Cn * 8, 128>>>(x, base_w, base_b, base_scale, wav_scale,
                                 w_ll, w_lh1, w_hl1, w_hh1,
                                 w_lh0, w_hl0, w_hh0, out);
}